// round 1
// baseline (speedup 1.0000x reference)
#include <cuda_runtime.h>

// PartialDerivatives: Jacobian (3x12) of a 3->64->64->64->64->12 SiLU MLP at N points.
// Warp-per-point scalar fp32 baseline:
//   - state (h, t0, t1, t2; each 64-wide) in registers: 2 floats per lane per vector
//   - k-broadcast via __shfl_sync
//   - W2..W4 staged in dynamic SMEM as float2 {W[k][c], W[k][c+32]} -> 1 LDS.64 per k feeds 8 FFMA
//   - layer 5 (64x12) via small per-warp SMEM tangent buffer
//
// Shared memory layout (floats):
//   [0,      4096)  W2 interleaved (float2[64][32])
//   [4096,   8192)  W3 interleaved
//   [8192,  12288)  W4 interleaved
//   [12288, 12480)  W1 (3x64 row-major)
//   [12480, 12544)  b1
//   [12544, 12736)  b2,b3,b4
//   [12736, 13504)  W5 (64x12 row-major)
//   [13504, 15136)  per-warp tangent buffers: 8 warps * 3 * 68 (padded stride)
#define PD_NWARPS 8
#define PD_THREADS (PD_NWARPS * 32)
#define PD_SMEM_FLOATS 15136
#define PD_TSTRIDE 68

__device__ __forceinline__ void pd_silu_d(float pre, float& h, float& d) {
    float sig = 1.0f / (1.0f + __expf(-pre));
    h = pre * sig;                     // silu(pre)
    d = fmaf(h, 1.0f - sig, sig);      // silu'(pre) = sig + pre*sig*(1-sig)
}

__device__ __forceinline__ void pd_layer(
    const float2* __restrict__ W, const float* __restrict__ bias, int lane,
    float& h0, float& h1,
    float& t00, float& t01,
    float& t10, float& t11,
    float& t20, float& t21)
{
    float aH0 = bias[lane], aH1 = bias[lane + 32];
    float aA0 = 0.f, aA1 = 0.f, aB0 = 0.f, aB1 = 0.f, aC0 = 0.f, aC1 = 0.f;

    #pragma unroll 16
    for (int k = 0; k < 32; ++k) {
        float2 w = W[k * 32 + lane];
        float hk = __shfl_sync(0xFFFFFFFFu, h0,  k);
        float ak = __shfl_sync(0xFFFFFFFFu, t00, k);
        float bk = __shfl_sync(0xFFFFFFFFu, t10, k);
        float ck = __shfl_sync(0xFFFFFFFFu, t20, k);
        aH0 = fmaf(hk, w.x, aH0); aH1 = fmaf(hk, w.y, aH1);
        aA0 = fmaf(ak, w.x, aA0); aA1 = fmaf(ak, w.y, aA1);
        aB0 = fmaf(bk, w.x, aB0); aB1 = fmaf(bk, w.y, aB1);
        aC0 = fmaf(ck, w.x, aC0); aC1 = fmaf(ck, w.y, aC1);
    }
    #pragma unroll 16
    for (int k = 32; k < 64; ++k) {
        float2 w = W[k * 32 + lane];
        float hk = __shfl_sync(0xFFFFFFFFu, h1,  k - 32);
        float ak = __shfl_sync(0xFFFFFFFFu, t01, k - 32);
        float bk = __shfl_sync(0xFFFFFFFFu, t11, k - 32);
        float ck = __shfl_sync(0xFFFFFFFFu, t21, k - 32);
        aH0 = fmaf(hk, w.x, aH0); aH1 = fmaf(hk, w.y, aH1);
        aA0 = fmaf(ak, w.x, aA0); aA1 = fmaf(ak, w.y, aA1);
        aB0 = fmaf(bk, w.x, aB0); aB1 = fmaf(bk, w.y, aB1);
        aC0 = fmaf(ck, w.x, aC0); aC1 = fmaf(ck, w.y, aC1);
    }

    float nh0, nh1, d0, d1;
    pd_silu_d(aH0, nh0, d0);
    pd_silu_d(aH1, nh1, d1);
    h0 = nh0; h1 = nh1;
    t00 = aA0 * d0; t01 = aA1 * d1;
    t10 = aB0 * d0; t11 = aB1 * d1;
    t20 = aC0 * d0; t21 = aC1 * d1;
}

__global__ void __launch_bounds__(PD_THREADS)
PartialDerivatives_38706245271665_kernel(
    const float* __restrict__ x,
    const float* __restrict__ W1, const float* __restrict__ b1,
    const float* __restrict__ W2, const float* __restrict__ b2,
    const float* __restrict__ W3, const float* __restrict__ b3,
    const float* __restrict__ W4, const float* __restrict__ b4,
    const float* __restrict__ W5,
    float* __restrict__ out, int N)
{
    extern __shared__ float smem[];
    float2* sWp  = (float2*)smem;            // 3 layers * 2048 float2
    float*  sW1  = smem + 12288;
    float*  sB1  = smem + 12480;
    float*  sB   = smem + 12544;             // b2,b3,b4
    float*  sW5  = smem + 12736;
    float*  sT   = smem + 13504;             // PD_NWARPS * 3 * PD_TSTRIDE

    // ---- cooperative weight staging ----
    {
        const float* Wg0 = W2;
        const float* Wg1 = W3;
        const float* Wg2 = W4;
        for (int i = threadIdx.x; i < 2048; i += blockDim.x) {
            int k = i >> 5, c = i & 31;
            sWp[i]        = make_float2(Wg0[k * 64 + c], Wg0[k * 64 + c + 32]);
            sWp[2048 + i] = make_float2(Wg1[k * 64 + c], Wg1[k * 64 + c + 32]);
            sWp[4096 + i] = make_float2(Wg2[k * 64 + c], Wg2[k * 64 + c + 32]);
        }
        for (int i = threadIdx.x; i < 192; i += blockDim.x) sW1[i] = W1[i];
        for (int i = threadIdx.x; i < 64;  i += blockDim.x) {
            sB1[i] = b1[i];
            sB[i] = b2[i]; sB[64 + i] = b3[i]; sB[128 + i] = b4[i];
        }
        for (int i = threadIdx.x; i < 768; i += blockDim.x) sW5[i] = W5[i];
    }
    __syncthreads();

    const int lane = threadIdx.x & 31;
    const int wid  = threadIdx.x >> 5;
    float* myT = sT + wid * (3 * PD_TSTRIDE);

    const int warpGlobal = blockIdx.x * PD_NWARPS + wid;
    const int warpStride = gridDim.x * PD_NWARPS;
    const int c0 = lane, c1 = lane + 32;

    for (int p = warpGlobal; p < N; p += warpStride) {
        float x0 = __ldg(x + 3 * (size_t)p);
        float x1 = __ldg(x + 3 * (size_t)p + 1);
        float x2 = __ldg(x + 3 * (size_t)p + 2);

        // ---- layer 1 (K=3), tangents init: t_j = W1[j,:] * d ----
        float wA0 = sW1[c0], wB0 = sW1[64 + c0], wC0 = sW1[128 + c0];
        float wA1 = sW1[c1], wB1 = sW1[64 + c1], wC1 = sW1[128 + c1];
        float p0 = fmaf(x0, wA0, fmaf(x1, wB0, fmaf(x2, wC0, sB1[c0])));
        float p1 = fmaf(x0, wA1, fmaf(x1, wB1, fmaf(x2, wC1, sB1[c1])));
        float h0, h1, d0, d1;
        pd_silu_d(p0, h0, d0);
        pd_silu_d(p1, h1, d1);
        float t00 = wA0 * d0, t01 = wA1 * d1;
        float t10 = wB0 * d0, t11 = wB1 * d1;
        float t20 = wC0 * d0, t21 = wC1 * d1;

        // ---- layers 2..4 ----
        pd_layer(sWp,        sB,        lane, h0, h1, t00, t01, t10, t11, t20, t21);
        pd_layer(sWp + 2048, sB + 64,   lane, h0, h1, t00, t01, t10, t11, t20, t21);
        pd_layer(sWp + 4096, sB + 128,  lane, h0, h1, t00, t01, t10, t11, t20, t21);

        // ---- layer 5: J[j][c] = sum_k t_j[k] * W5[k][c], c in [0,12) ----
        __syncwarp();
        myT[0 * PD_TSTRIDE + c0] = t00; myT[0 * PD_TSTRIDE + c1] = t01;
        myT[1 * PD_TSTRIDE + c0] = t10; myT[1 * PD_TSTRIDE + c1] = t11;
        myT[2 * PD_TSTRIDE + c0] = t20; myT[2 * PD_TSTRIDE + c1] = t21;
        __syncwarp();

        float* outp = out + 36 * (size_t)p;
        for (int idx = lane; idx < 36; idx += 32) {
            int j = idx / 12;
            int cc = idx - 12 * j;
            const float* tj = myT + j * PD_TSTRIDE;
            float acc = 0.f;
            #pragma unroll 16
            for (int k = 0; k < 64; ++k)
                acc = fmaf(tj[k], sW5[k * 12 + cc], acc);
            outp[idx] = acc;
        }
        __syncwarp();
    }
}

extern "C" void kernel_launch(void* const* d_in, const int* in_sizes, int n_in,
                              void* d_out, int out_size)
{
    const float* x  = (const float*)d_in[0];
    const float* W1 = (const float*)d_in[1];
    const float* b1 = (const float*)d_in[2];
    const float* W2 = (const float*)d_in[3];
    const float* b2 = (const float*)d_in[4];
    const float* W3 = (const float*)d_in[5];
    const float* b3 = (const float*)d_in[6];
    const float* W4 = (const float*)d_in[7];
    const float* b4 = (const float*)d_in[8];
    const float* W5 = (const float*)d_in[9];
    // b5 unused: d(out + b5)/dx has no b5 term.

    int N = in_sizes[0] / 3;
    int smemBytes = PD_SMEM_FLOATS * (int)sizeof(float);

    cudaFuncSetAttribute(PartialDerivatives_38706245271665_kernel,
                         cudaFuncAttributeMaxDynamicSharedMemorySize, smemBytes);

    int blocks = 912;  // 152 SMs * 3 CTAs/SM * 2 waves
    PartialDerivatives_38706245271665_kernel<<<blocks, PD_THREADS, smemBytes>>>(
        x, W1, b1, W2, b2, W3, b3, W4, b4, W5, (float*)d_out, N);
}

// round 2
// speedup vs baseline: 3.4932x; 3.4932x over previous
#include <cuda_runtime.h>
#include <cuda_bf16.h>
#include <string.h>

// Jacobian (3x12) of 3->64->64->64->64->12 SiLU MLP at N points.
// Tensor-core version: mma.sync m16n8k16 bf16 with 2-way bf16 split (3 MMAs per product,
// fp32 accumulate; dropped lo*lo term -> ~1e-5 rel err).
//
// Per warp: 16-point tile. 4 vectors (h, t0, t1, t2) share identical fragment layouts,
// so silu' coupling is register-local. Activations live in per-warp SMEM as packed
// bf16 hi/lo pairs in A-fragment layout; weights packed once per CTA in B-fragment layout.
//
// SMEM word layout (4-byte words):
//   [0,192)        W1 fp32 (3x64)
//   [192,256)      b1
//   [256,448)      b2,b3,b4
//   [448,1216)     W5 hi packed (32 kp x stride24, cols padded to 16)
//   [1216,1984)    W5 lo
//   [1984,8896)    W2..W4 hi packed (3 x 32 kp x stride72)
//   [8896,15808)   W2..W4 lo
//   [15808,...)    per-warp activation buffers: 8 warps x 4608 words
//                  (Ahi[4 vec][16 rows][stride36], then Alo same)

#define PD_NW 8
#define PD_THREADS (PD_NW * 32)
#define PD_SMEM_WORDS (15808 + PD_NW * 4608)

__device__ __forceinline__ unsigned pd_u32(__nv_bfloat162 v) {
    unsigned r; memcpy(&r, &v, 4); return r;
}

// Split (x,y) into packed bf16 hi pair and residual lo pair.
__device__ __forceinline__ void pd_split2(float xf, float yf, unsigned& hi, unsigned& lo) {
    __nv_bfloat16 xh = __float2bfloat16(xf);
    __nv_bfloat16 yh = __float2bfloat16(yf);
    float xr = xf - __bfloat162float(xh);
    float yr = yf - __bfloat162float(yh);
    hi = pd_u32(__halves2bfloat162(xh, yh));
    lo = pd_u32(__floats2bfloat162_rn(xr, yr));
}

__device__ __forceinline__ void pd_mma(float* d,
                                       unsigned a0, unsigned a1, unsigned a2, unsigned a3,
                                       unsigned b0, unsigned b1) {
    asm volatile(
        "mma.sync.aligned.m16n8k16.row.col.f32.bf16.bf16.f32 "
        "{%0,%1,%2,%3},{%4,%5,%6,%7},{%8,%9},{%0,%1,%2,%3};\n"
        : "+f"(d[0]), "+f"(d[1]), "+f"(d[2]), "+f"(d[3])
        : "r"(a0), "r"(a1), "r"(a2), "r"(a3), "r"(b0), "r"(b1));
}

__device__ __forceinline__ void pd_silu_d(float pre, float& h, float& d) {
    float sig = 1.0f / (1.0f + __expf(-pre));
    h = pre * sig;
    d = fmaf(h, 1.0f - sig, sig);
}

__global__ void __launch_bounds__(PD_THREADS, 1)
PartialDerivatives_38706245271665_kernel(
    const float* __restrict__ x,
    const float* __restrict__ W1, const float* __restrict__ b1,
    const float* __restrict__ W2, const float* __restrict__ b2,
    const float* __restrict__ W3, const float* __restrict__ b3,
    const float* __restrict__ W4, const float* __restrict__ b4,
    const float* __restrict__ W5,
    float* __restrict__ out, int N)
{
    extern __shared__ unsigned sm[];
    float*    fW1 = (float*)sm;              // 192
    float*    fB1 = (float*)(sm + 192);      // 64
    float*    fB  = (float*)(sm + 256);      // 192 (b2,b3,b4)
    unsigned* W5h = sm + 448;                // 768
    unsigned* W5l = sm + 1216;               // 768
    unsigned* Wh  = sm + 1984;               // 3*2304
    unsigned* Wl  = sm + 8896;               // 3*2304
    unsigned* Ab  = sm + 15808;              // per warp 4608

    const int tid = threadIdx.x;

    // ---- one-time weight staging / packing ----
    for (int i = tid; i < 192; i += PD_THREADS) fW1[i] = W1[i];
    for (int i = tid; i < 64;  i += PD_THREADS) {
        fB1[i] = b1[i]; fB[i] = b2[i]; fB[64 + i] = b3[i]; fB[128 + i] = b4[i];
    }
    {
        const float* Ws[3] = {W2, W3, W4};
        for (int i = tid; i < 2048; i += PD_THREADS) {
            int kp = i >> 6, n = i & 63;
            #pragma unroll
            for (int l = 0; l < 3; ++l) {
                float v0 = Ws[l][(2 * kp) * 64 + n];
                float v1 = Ws[l][(2 * kp + 1) * 64 + n];
                unsigned hi, lo; pd_split2(v0, v1, hi, lo);
                Wh[l * 2304 + kp * 72 + n] = hi;
                Wl[l * 2304 + kp * 72 + n] = lo;
            }
        }
        for (int i = tid; i < 512; i += PD_THREADS) {
            int kp = i >> 4, n = i & 15;
            float v0 = (n < 12) ? W5[(2 * kp) * 12 + n] : 0.0f;
            float v1 = (n < 12) ? W5[(2 * kp + 1) * 12 + n] : 0.0f;
            unsigned hi, lo; pd_split2(v0, v1, hi, lo);
            W5h[kp * 24 + n] = hi;
            W5l[kp * 24 + n] = lo;
        }
    }
    __syncthreads();

    const int wid  = tid >> 5;
    const int lane = tid & 31;
    const int g    = lane >> 2;   // group: row within 8-row block / B col
    const int tg   = lane & 3;    // thread-in-group

    unsigned* Ah = Ab + wid * 4608;   // Ahi[vec] = Ah + vec*576 (16 rows x stride 36)
    unsigned* Al = Ah + 2304;

    const int nTiles = (N + 15) >> 4;

    for (int wt = blockIdx.x * PD_NW + wid; wt < nTiles; wt += gridDim.x * PD_NW) {
        const int p0 = wt << 4;

        // ================= layer 1 (K=3), scalar, fills Abuf =================
        {
            int pl = lane >> 1;
            int p  = p0 + pl;
            float x0 = 0.f, x1 = 0.f, x2 = 0.f;
            if (p < N) {
                const float* xp = x + 3 * (size_t)p;
                x0 = __ldg(xp); x1 = __ldg(xp + 1); x2 = __ldg(xp + 2);
            }
            int half = (lane & 1) * 32;
            #pragma unroll
            for (int i = 0; i < 16; ++i) {
                int c0 = half + 2 * i, c1 = c0 + 1;
                float wa0 = fW1[c0], wb0 = fW1[64 + c0], wc0 = fW1[128 + c0];
                float wa1 = fW1[c1], wb1 = fW1[64 + c1], wc1 = fW1[128 + c1];
                float pr0 = fmaf(x0, wa0, fmaf(x1, wb0, fmaf(x2, wc0, fB1[c0])));
                float pr1 = fmaf(x0, wa1, fmaf(x1, wb1, fmaf(x2, wc1, fB1[c1])));
                float h0, d0, h1, d1;
                pd_silu_d(pr0, h0, d0);
                pd_silu_d(pr1, h1, d1);
                int idx = pl * 36 + (half >> 1) + i;
                unsigned hi, lo;
                pd_split2(h0, h1, hi, lo);           Ah[idx] = hi;        Al[idx] = lo;
                pd_split2(wa0 * d0, wa1 * d1, hi, lo); Ah[576 + idx] = hi;  Al[576 + idx] = lo;
                pd_split2(wb0 * d0, wb1 * d1, hi, lo); Ah[1152 + idx] = hi; Al[1152 + idx] = lo;
                pd_split2(wc0 * d0, wc1 * d1, hi, lo); Ah[1728 + idx] = hi; Al[1728 + idx] = lo;
            }
        }
        __syncwarp();

        // ================= layers 2..4: 64x64 MMA + silu' epilogue =================
        #pragma unroll 1
        for (int L = 0; L < 3; ++L) {
            const unsigned* WH  = Wh + L * 2304;
            const unsigned* WLo = Wl + L * 2304;
            const float*    bias = fB + L * 64;

            float acc[4][8][4];
            #pragma unroll
            for (int v = 0; v < 4; ++v)
                #pragma unroll
                for (int nt = 0; nt < 8; ++nt)
                    #pragma unroll
                    for (int q = 0; q < 4; ++q) acc[v][nt][q] = 0.f;

            #pragma unroll
            for (int kt = 0; kt < 4; ++kt) {
                unsigned bh[8][2], bl[8][2];
                #pragma unroll
                for (int nt = 0; nt < 8; ++nt) {
                    int n = 8 * nt + g;
                    bh[nt][0] = WH [(8 * kt + tg) * 72 + n];
                    bh[nt][1] = WH [(8 * kt + tg + 4) * 72 + n];
                    bl[nt][0] = WLo[(8 * kt + tg) * 72 + n];
                    bl[nt][1] = WLo[(8 * kt + tg + 4) * 72 + n];
                }
                #pragma unroll
                for (int v = 0; v < 4; ++v) {
                    const unsigned* AH  = Ah + v * 576;
                    const unsigned* ALo = Al + v * 576;
                    int i0 = g * 36 + tg + 8 * kt;
                    int i1 = i0 + 8 * 36;
                    unsigned ah0 = AH[i0], ah1 = AH[i1], ah2 = AH[i0 + 4], ah3 = AH[i1 + 4];
                    unsigned al0 = ALo[i0], al1 = ALo[i1], al2 = ALo[i0 + 4], al3 = ALo[i1 + 4];
                    #pragma unroll
                    for (int nt = 0; nt < 8; ++nt)
                        pd_mma(acc[v][nt], ah0, ah1, ah2, ah3, bh[nt][0], bh[nt][1]);
                    #pragma unroll
                    for (int nt = 0; nt < 8; ++nt)
                        pd_mma(acc[v][nt], ah0, ah1, ah2, ah3, bl[nt][0], bl[nt][1]);
                    #pragma unroll
                    for (int nt = 0; nt < 8; ++nt)
                        pd_mma(acc[v][nt], al0, al1, al2, al3, bh[nt][0], bh[nt][1]);
                }
            }
            __syncwarp();

            // epilogue: bias + silu on h, scale tangents by d, repack to Abuf
            #pragma unroll
            for (int nt = 0; nt < 8; ++nt) {
                int cc = 8 * nt + 2 * tg;
                float bb0 = bias[cc], bb1 = bias[cc + 1];
                float pr0 = acc[0][nt][0] + bb0;
                float pr1 = acc[0][nt][1] + bb1;
                float pr2 = acc[0][nt][2] + bb0;
                float pr3 = acc[0][nt][3] + bb1;
                float h0, d0, h1, d1, h2, d2, h3, d3;
                pd_silu_d(pr0, h0, d0);
                pd_silu_d(pr1, h1, d1);
                pd_silu_d(pr2, h2, d2);
                pd_silu_d(pr3, h3, d3);

                int ia = g * 36 + 4 * nt + tg;
                int ib = ia + 8 * 36;
                unsigned hi, lo;
                pd_split2(h0, h1, hi, lo); Ah[ia] = hi; Al[ia] = lo;
                pd_split2(h2, h3, hi, lo); Ah[ib] = hi; Al[ib] = lo;
                #pragma unroll
                for (int v = 1; v < 4; ++v) {
                    float t0 = acc[v][nt][0] * d0;
                    float t1 = acc[v][nt][1] * d1;
                    float t2 = acc[v][nt][2] * d2;
                    float t3 = acc[v][nt][3] * d3;
                    pd_split2(t0, t1, hi, lo); Ah[v * 576 + ia] = hi; Al[v * 576 + ia] = lo;
                    pd_split2(t2, t3, hi, lo); Ah[v * 576 + ib] = hi; Al[v * 576 + ib] = lo;
                }
            }
            __syncwarp();
        }

        // ================= layer 5: [16x64] @ [64x12(pad16)] =================
        {
            float acc[3][2][4];
            #pragma unroll
            for (int v = 0; v < 3; ++v)
                #pragma unroll
                for (int nt = 0; nt < 2; ++nt)
                    #pragma unroll
                    for (int q = 0; q < 4; ++q) acc[v][nt][q] = 0.f;

            #pragma unroll
            for (int kt = 0; kt < 4; ++kt) {
                unsigned bh[2][2], bl[2][2];
                #pragma unroll
                for (int nt = 0; nt < 2; ++nt) {
                    int n = 8 * nt + g;
                    bh[nt][0] = W5h[(8 * kt + tg) * 24 + n];
                    bh[nt][1] = W5h[(8 * kt + tg + 4) * 24 + n];
                    bl[nt][0] = W5l[(8 * kt + tg) * 24 + n];
                    bl[nt][1] = W5l[(8 * kt + tg + 4) * 24 + n];
                }
                #pragma unroll
                for (int v = 0; v < 3; ++v) {
                    const unsigned* AH  = Ah + (v + 1) * 576;
                    const unsigned* ALo = Al + (v + 1) * 576;
                    int i0 = g * 36 + tg + 8 * kt;
                    int i1 = i0 + 8 * 36;
                    unsigned ah0 = AH[i0], ah1 = AH[i1], ah2 = AH[i0 + 4], ah3 = AH[i1 + 4];
                    unsigned al0 = ALo[i0], al1 = ALo[i1], al2 = ALo[i0 + 4], al3 = ALo[i1 + 4];
                    #pragma unroll
                    for (int nt = 0; nt < 2; ++nt) {
                        pd_mma(acc[v][nt], ah0, ah1, ah2, ah3, bh[nt][0], bh[nt][1]);
                        pd_mma(acc[v][nt], ah0, ah1, ah2, ah3, bl[nt][0], bl[nt][1]);
                        pd_mma(acc[v][nt], al0, al1, al2, al3, bh[nt][0], bh[nt][1]);
                    }
                }
            }
            __syncwarp();

            // direct fragment -> gmem stores (cols < 12 only)
            int pA = p0 + g, pB = p0 + g + 8;
            #pragma unroll
            for (int v = 0; v < 3; ++v) {
                #pragma unroll
                for (int nt = 0; nt < 2; ++nt) {
                    int cc = 8 * nt + 2 * tg;
                    if (cc <= 10) {
                        if (pA < N) {
                            float2* dst = (float2*)(out + 36 * (size_t)pA + 12 * v + cc);
                            *dst = make_float2(acc[v][nt][0], acc[v][nt][1]);
                        }
                        if (pB < N) {
                            float2* dst = (float2*)(out + 36 * (size_t)pB + 12 * v + cc);
                            *dst = make_float2(acc[v][nt][2], acc[v][nt][3]);
                        }
                    }
                }
            }
        }
        __syncwarp();
    }
}

extern "C" void kernel_launch(void* const* d_in, const int* in_sizes, int n_in,
                              void* d_out, int out_size)
{
    const float* x  = (const float*)d_in[0];
    const float* W1 = (const float*)d_in[1];
    const float* b1 = (const float*)d_in[2];
    const float* W2 = (const float*)d_in[3];
    const float* b2 = (const float*)d_in[4];
    const float* W3 = (const float*)d_in[5];
    const float* b3 = (const float*)d_in[6];
    const float* W4 = (const float*)d_in[7];
    const float* b4 = (const float*)d_in[8];
    const float* W5 = (const float*)d_in[9];
    // b5 unused: constant offset has zero Jacobian.

    int N = in_sizes[0] / 3;
    int smemBytes = PD_SMEM_WORDS * (int)sizeof(unsigned);

    cudaFuncSetAttribute(PartialDerivatives_38706245271665_kernel,
                         cudaFuncAttributeMaxDynamicSharedMemorySize, smemBytes);

    PartialDerivatives_38706245271665_kernel<<<152, PD_THREADS, smemBytes>>>(
        x, W1, b1, W2, b2, W3, b3, W4, b4, W5, (float*)d_out, N);
}

// round 4
// speedup vs baseline: 3.5371x; 1.0126x over previous
#include <cuda_runtime.h>
#include <cuda_bf16.h>
#include <cstdint>

// Jacobian (3x12) of 3->64->64->64->64->12 SiLU MLP at N=1M points.
// Warp-level mma.sync m16n8k16 bf16, 2-way bf16 split (3 MMA terms, fp32 accum).
// KEY: D-accumulator fragments map register-locally onto next layer's A fragments
// (pair of adjacent n-tiles = one k-block), so activations NEVER touch SMEM.
// SMEM holds only weights, pre-split and pre-packed in B-fragment order.
//
// Per warp: 16-point tile. Fragments: Ah/Al[4 vec][4 kblk * 4 frags].
// Weights layout (u32 words):
//   [0,192)        W1 (3x64 f32)
//   [192,448)      b1,b2,b3,b4
//   [448,12736)    B' layers 2..4: per layer 4096 words (hi 2048 | lo 2048),
//                  word (kt*32+tg*8+g)*16 + 2*nt + r = pack(W[16kt+2tg+8r][8nt+g], W[+1][..])
//   [12736,13760)  B5' (W5 padded to n=16): hi 512 | lo 512, 4 words per (kt,tg,g)
#define PD_NW 8
#define PD_THREADS 256
#define SM_W1   0
#define SM_BIAS 192
#define SM_B    448
#define SM_B5   12736
#define SM_WORDS 13760

__device__ __forceinline__ void pd_mma(float* d,
                                       uint32_t a0, uint32_t a1, uint32_t a2, uint32_t a3,
                                       uint32_t b0, uint32_t b1) {
    asm volatile(
        "mma.sync.aligned.m16n8k16.row.col.f32.bf16.bf16.f32 "
        "{%0,%1,%2,%3},{%4,%5,%6,%7},{%8,%9},{%0,%1,%2,%3};\n"
        : "+f"(d[0]), "+f"(d[1]), "+f"(d[2]), "+f"(d[3])
        : "r"(a0), "r"(a1), "r"(a2), "r"(a3), "r"(b0), "r"(b1));
}

// 8 n-tiles of one k-block: B frags packed as uint4 pairs {nt.b0, nt.b1, nt+1.b0, nt+1.b1}
__device__ __forceinline__ void pd_mma8(float* acc, const uint32_t* a,
                                        uint4 B0, uint4 B1, uint4 B2, uint4 B3) {
    pd_mma(acc + 0,  a[0], a[1], a[2], a[3], B0.x, B0.y);
    pd_mma(acc + 4,  a[0], a[1], a[2], a[3], B0.z, B0.w);
    pd_mma(acc + 8,  a[0], a[1], a[2], a[3], B1.x, B1.y);
    pd_mma(acc + 12, a[0], a[1], a[2], a[3], B1.z, B1.w);
    pd_mma(acc + 16, a[0], a[1], a[2], a[3], B2.x, B2.y);
    pd_mma(acc + 20, a[0], a[1], a[2], a[3], B2.z, B2.w);
    pd_mma(acc + 24, a[0], a[1], a[2], a[3], B3.x, B3.y);
    pd_mma(acc + 28, a[0], a[1], a[2], a[3], B3.z, B3.w);
}

__device__ __forceinline__ void pd_silu_d(float pre, float& h, float& d) {
    float sig = 1.0f / (1.0f + __expf(-pre));
    h = pre * sig;
    d = fmaf(h, 1.0f - sig, sig);   // silu' = sig + pre*sig*(1-sig)
}

// pack (f0 -> low half, f1 -> high half) to bf16x2 hi; residuals to lo
__device__ __forceinline__ void pd_split2(float f0, float f1, uint32_t& hi, uint32_t& lo) {
    uint32_t h;
    asm("cvt.rn.bf16x2.f32 %0, %1, %2;" : "=r"(h) : "f"(f1), "f"(f0));
    float r0 = f0 - __uint_as_float(h << 16);
    float r1 = f1 - __uint_as_float(h & 0xFFFF0000u);
    uint32_t l;
    asm("cvt.rn.bf16x2.f32 %0, %1, %2;" : "=r"(l) : "f"(r1), "f"(r0));
    hi = h; lo = l;
}

// D-layout vals[32] (= acc) -> A fragments [16] (hi/lo). nt pair (2kt,2kt+1) = k-block kt.
__device__ __forceinline__ void pd_pack(const float* v, uint32_t* ah, uint32_t* al) {
    #pragma unroll
    for (int kt = 0; kt < 4; ++kt) {
        pd_split2(v[8 * kt + 0], v[8 * kt + 1], ah[4 * kt + 0], al[4 * kt + 0]); // a0
        pd_split2(v[8 * kt + 2], v[8 * kt + 3], ah[4 * kt + 1], al[4 * kt + 1]); // a1
        pd_split2(v[8 * kt + 4], v[8 * kt + 5], ah[4 * kt + 2], al[4 * kt + 2]); // a2
        pd_split2(v[8 * kt + 6], v[8 * kt + 7], ah[4 * kt + 3], al[4 * kt + 3]); // a3
    }
}

__global__ void __launch_bounds__(PD_THREADS)
PartialDerivatives_38706245271665_kernel(
    const float* __restrict__ x,
    const float* __restrict__ W1, const float* __restrict__ b1,
    const float* __restrict__ W2, const float* __restrict__ b2,
    const float* __restrict__ W3, const float* __restrict__ b3,
    const float* __restrict__ W4, const float* __restrict__ b4,
    const float* __restrict__ W5,
    float* __restrict__ out, int N)
{
    __shared__ uint32_t sm[SM_WORDS];
    float* sW1   = (float*)(sm + SM_W1);
    float* sBias = (float*)(sm + SM_BIAS);
    const int tid = threadIdx.x;

    // ---- stage W1 / biases ----
    for (int i = tid; i < 192; i += PD_THREADS) sW1[i] = W1[i];
    for (int i = tid; i < 64; i += PD_THREADS) {
        sBias[i] = b1[i]; sBias[64 + i] = b2[i];
        sBias[128 + i] = b3[i]; sBias[192 + i] = b4[i];
    }
    // ---- stage B' (fragment-ordered, bf16 hi/lo split) ----
    for (int i = tid; i < 3 * 2048; i += PD_THREADS) {
        int L = i >> 11, r = i & 2047;
        int idx = r >> 4, j = r & 15;
        int kt = idx >> 5, tg_ = (idx >> 3) & 3, g_ = idx & 7;
        int nt = j >> 1, rr = j & 1;
        int k0 = 16 * kt + 2 * tg_ + 8 * rr;
        int n  = 8 * nt + g_;
        const float* W = (L == 0) ? W2 : (L == 1) ? W3 : W4;
        uint32_t hi, lo;
        pd_split2(W[k0 * 64 + n], W[(k0 + 1) * 64 + n], hi, lo);
        sm[SM_B + L * 4096 + idx * 16 + j] = hi;
        sm[SM_B + L * 4096 + 2048 + idx * 16 + j] = lo;
    }
    for (int i = tid; i < 512; i += PD_THREADS) {
        int idx = i >> 2, j = i & 3;
        int kt = idx >> 5, tg_ = (idx >> 3) & 3, g_ = idx & 7;
        int nt = j >> 1, rr = j & 1;
        int k0 = 16 * kt + 2 * tg_ + 8 * rr;
        int n  = 8 * nt + g_;
        float v0 = (n < 12) ? W5[k0 * 12 + n] : 0.0f;
        float v1 = (n < 12) ? W5[(k0 + 1) * 12 + n] : 0.0f;
        uint32_t hi, lo;
        pd_split2(v0, v1, hi, lo);
        sm[SM_B5 + idx * 4 + j] = hi;
        sm[SM_B5 + 512 + idx * 4 + j] = lo;
    }
    __syncthreads();

    const int wid  = tid >> 5;
    const int lane = tid & 31;
    const int g    = lane >> 2;
    const int tg   = lane & 3;

    const int nTiles = (N + 15) >> 4;
    const int warp0  = blockIdx.x * PD_NW + wid;
    const int wstep  = gridDim.x * PD_NW;

    for (int wt = warp0; wt < nTiles; wt += wstep) {
        const int p0 = wt << 4;
        const int pA = p0 + g, pB = p0 + g + 8;

        uint32_t Ah[4][16], Al[4][16];

        // ================ layer 1 (K=3), direct into fragments ================
        {
            float xA0 = 0.f, xA1 = 0.f, xA2 = 0.f, xB0 = 0.f, xB1 = 0.f, xB2 = 0.f;
            if (pA < N) {
                const float* xp = x + 3 * (size_t)pA;
                xA0 = __ldg(xp); xA1 = __ldg(xp + 1); xA2 = __ldg(xp + 2);
            }
            if (pB < N) {
                const float* xp = x + 3 * (size_t)pB;
                xB0 = __ldg(xp); xB1 = __ldg(xp + 1); xB2 = __ldg(xp + 2);
            }
            #pragma unroll
            for (int kt = 0; kt < 4; ++kt) {
                #pragma unroll
                for (int s = 0; s < 2; ++s) {
                    int f0 = 16 * kt + 2 * tg + 8 * s;
                    float2 w0 = *(float2*)&sW1[f0];
                    float2 w1 = *(float2*)&sW1[64 + f0];
                    float2 w2 = *(float2*)&sW1[128 + f0];
                    float2 bb = *(float2*)&sBias[f0];
                    float hA0, dA0, hA1, dA1, hB0, dB0, hB1, dB1;
                    pd_silu_d(fmaf(xA0, w0.x, fmaf(xA1, w1.x, fmaf(xA2, w2.x, bb.x))), hA0, dA0);
                    pd_silu_d(fmaf(xA0, w0.y, fmaf(xA1, w1.y, fmaf(xA2, w2.y, bb.y))), hA1, dA1);
                    pd_silu_d(fmaf(xB0, w0.x, fmaf(xB1, w1.x, fmaf(xB2, w2.x, bb.x))), hB0, dB0);
                    pd_silu_d(fmaf(xB0, w0.y, fmaf(xB1, w1.y, fmaf(xB2, w2.y, bb.y))), hB1, dB1);
                    int fr = kt * 4 + 2 * s;
                    pd_split2(hA0, hA1, Ah[0][fr], Al[0][fr]);
                    pd_split2(hB0, hB1, Ah[0][fr + 1], Al[0][fr + 1]);
                    pd_split2(w0.x * dA0, w0.y * dA1, Ah[1][fr], Al[1][fr]);
                    pd_split2(w0.x * dB0, w0.y * dB1, Ah[1][fr + 1], Al[1][fr + 1]);
                    pd_split2(w1.x * dA0, w1.y * dA1, Ah[2][fr], Al[2][fr]);
                    pd_split2(w1.x * dB0, w1.y * dB1, Ah[2][fr + 1], Al[2][fr + 1]);
                    pd_split2(w2.x * dA0, w2.y * dA1, Ah[3][fr], Al[3][fr]);
                    pd_split2(w2.x * dB0, w2.y * dB1, Ah[3][fr + 1], Al[3][fr + 1]);
                }
            }
        }

        // ================ layers 2..4: MMA + register-local epilogue ================
        #pragma unroll 1
        for (int L = 0; L < 3; ++L) {
            const uint32_t* BH = sm + SM_B + L * 4096;
            const float* bias  = sBias + 64 + L * 64;
            const bool lastL   = (L == 2);
            float dv[32];

            #pragma unroll
            for (int v = 0; v < 4; ++v) {
                float acc[32];
                #pragma unroll
                for (int q = 0; q < 32; ++q) acc[q] = 0.f;

                #pragma unroll
                for (int kt = 0; kt < 4; ++kt) {
                    const uint4* hp = (const uint4*)(BH + (kt * 32 + tg * 8 + g) * 16);
                    uint4 B0 = hp[0], B1 = hp[1], B2 = hp[2], B3 = hp[3];
                    pd_mma8(acc, &Ah[v][kt * 4], B0, B1, B2, B3);   // hi*hi
                    pd_mma8(acc, &Al[v][kt * 4], B0, B1, B2, B3);   // lo*hi
                    const uint4* lp = (const uint4*)(BH + 2048 + (kt * 32 + tg * 8 + g) * 16);
                    B0 = lp[0]; B1 = lp[1]; B2 = lp[2]; B3 = lp[3];
                    pd_mma8(acc, &Ah[v][kt * 4], B0, B1, B2, B3);   // hi*lo
                }

                if (v == 0) {
                    #pragma unroll
                    for (int nt = 0; nt < 8; ++nt) {
                        float2 bb = *(float2*)&bias[8 * nt + 2 * tg];
                        float h0, h1, h2, h3;
                        pd_silu_d(acc[4 * nt + 0] + bb.x, h0, dv[4 * nt + 0]);
                        pd_silu_d(acc[4 * nt + 1] + bb.y, h1, dv[4 * nt + 1]);
                        pd_silu_d(acc[4 * nt + 2] + bb.x, h2, dv[4 * nt + 2]);
                        pd_silu_d(acc[4 * nt + 3] + bb.y, h3, dv[4 * nt + 3]);
                        acc[4 * nt + 0] = h0; acc[4 * nt + 1] = h1;
                        acc[4 * nt + 2] = h2; acc[4 * nt + 3] = h3;
                    }
                    if (!lastL) pd_pack(acc, Ah[0], Al[0]);   // h not needed after L4
                } else {
                    #pragma unroll
                    for (int q = 0; q < 32; ++q) acc[q] *= dv[q];
                    pd_pack(acc, Ah[v], Al[v]);
                }
            }
        }

        // ================ layer 5: tangents @ W5 (n padded to 16) ================
        {
            float a5[3][8];
            #pragma unroll
            for (int v = 0; v < 3; ++v)
                #pragma unroll
                for (int q = 0; q < 8; ++q) a5[v][q] = 0.f;

            #pragma unroll
            for (int kt = 0; kt < 4; ++kt) {
                const uint4* hp = (const uint4*)(sm + SM_B5 + (kt * 32 + tg * 8 + g) * 4);
                const uint4* lp = (const uint4*)(sm + SM_B5 + 512 + (kt * 32 + tg * 8 + g) * 4);
                uint4 H = hp[0], Lo = lp[0];
                #pragma unroll
                for (int v = 0; v < 3; ++v) {
                    const uint32_t* ah = &Ah[1 + v][kt * 4];
                    const uint32_t* al = &Al[1 + v][kt * 4];
                    pd_mma(a5[v] + 0, ah[0], ah[1], ah[2], ah[3], H.x, H.y);
                    pd_mma(a5[v] + 4, ah[0], ah[1], ah[2], ah[3], H.z, H.w);
                    pd_mma(a5[v] + 0, al[0], al[1], al[2], al[3], H.x, H.y);
                    pd_mma(a5[v] + 4, al[0], al[1], al[2], al[3], H.z, H.w);
                    pd_mma(a5[v] + 0, ah[0], ah[1], ah[2], ah[3], Lo.x, Lo.y);
                    pd_mma(a5[v] + 4, ah[0], ah[1], ah[2], ah[3], Lo.z, Lo.w);
                }
            }

            if (pA < N) {
                float* oA = out + 36 * (size_t)pA;
                #pragma unroll
                for (int v = 0; v < 3; ++v) {
                    *(float2*)(oA + 12 * v + 2 * tg) = make_float2(a5[v][0], a5[v][1]);
                    if (tg < 2)
                        *(float2*)(oA + 12 * v + 8 + 2 * tg) = make_float2(a5[v][4], a5[v][5]);
                }
            }
            if (pB < N) {
                float* oB = out + 36 * (size_t)pB;
                #pragma unroll
                for (int v = 0; v < 3; ++v) {
                    *(float2*)(oB + 12 * v + 2 * tg) = make_float2(a5[v][2], a5[v][3]);
                    if (tg < 2)
                        *(float2*)(oB + 12 * v + 8 + 2 * tg) = make_float2(a5[v][6], a5[v][7]);
                }
            }
        }
    }
}

extern "C" void kernel_launch(void* const* d_in, const int* in_sizes, int n_in,
                              void* d_out, int out_size)
{
    const float* x  = (const float*)d_in[0];
    const float* W1 = (const float*)d_in[1];
    const float* b1 = (const float*)d_in[2];
    const float* W2 = (const float*)d_in[3];
    const float* b2 = (const float*)d_in[4];
    const float* W3 = (const float*)d_in[5];
    const float* b3 = (const float*)d_in[6];
    const float* W4 = (const float*)d_in[7];
    const float* b4 = (const float*)d_in[8];
    const float* W5 = (const float*)d_in[9];
    // b5 unused: constant offset has zero Jacobian.

    int N = in_sizes[0] / 3;
    PartialDerivatives_38706245271665_kernel<<<152, PD_THREADS>>>(
        x, W1, b1, W2, b2, W3, b3, W4, b4, W5, (float*)d_out, N);
}